// round 11
// baseline (speedup 1.0000x reference)
#include <cuda_runtime.h>
#include <cuda_fp16.h>
#include <cstdint>
#include <math.h>

constexpr int Tn  = 2048;
constexpr int Hn  = 2048;
constexpr int In  = 1024;
constexpr int En  = 8;
constexpr int ISn = 2048;
constexpr int Rn  = 4096;

// ------------------------- scratch (device globals) -------------------------
__device__ float  g_yr [(size_t)Rn * Hn];
__device__ __half c_x  [(size_t)Tn * Hn];
__device__ __half c_hr [(size_t)Rn * In];
__device__ __half c_hs [(size_t)Tn * ISn];
__device__ int   g_tok[Rn];
__device__ float g_w  [Rn];
__device__ int   g_slot[Rn];
__device__ int   g_topk_i[Rn];
__device__ float g_topk_w[Rn];
__device__ int   g_cnt[En], g_off[En];

// ------------------------- PTX helpers --------------------------------------
__device__ __forceinline__ uint32_t smem_u32(const void* p) {
    uint32_t a;
    asm("{ .reg .u64 t; cvta.to.shared.u64 t, %1; cvt.u32.u64 %0, t; }" : "=r"(a) : "l"(p));
    return a;
}
__device__ __forceinline__ void cpa16(uint32_t dst, const void* src) {
    asm volatile("cp.async.cg.shared.global [%0], [%1], 16;" :: "r"(dst), "l"(src));
}
__device__ __forceinline__ void ldsm4(uint32_t* d, uint32_t a) {
    asm volatile("ldmatrix.sync.aligned.m8n8.x4.shared.b16 {%0,%1,%2,%3},[%4];"
                 : "=r"(d[0]), "=r"(d[1]), "=r"(d[2]), "=r"(d[3]) : "r"(a));
}
__device__ __forceinline__ void ldsm4t(uint32_t* d, uint32_t a) {
    asm volatile("ldmatrix.sync.aligned.m8n8.x4.trans.shared.b16 {%0,%1,%2,%3},[%4];"
                 : "=r"(d[0]), "=r"(d[1]), "=r"(d[2]), "=r"(d[3]) : "r"(a));
}
__device__ __forceinline__ void mma16(float* c, const uint32_t* a, const uint32_t* b) {
    asm volatile(
        "mma.sync.aligned.m16n8k16.row.col.f32.f16.f16.f32 "
        "{%0,%1,%2,%3},{%4,%5,%6,%7},{%8,%9},{%0,%1,%2,%3};"
        : "+f"(c[0]), "+f"(c[1]), "+f"(c[2]), "+f"(c[3])
        : "r"(a[0]), "r"(a[1]), "r"(a[2]), "r"(a[3]), "r"(b[0]), "r"(b[1]));
}
__device__ __forceinline__ uint32_t h2u(float a, float b) {
    __half2 h = __floats2half2_rn(a, b);
    return *reinterpret_cast<uint32_t*>(&h);
}

// ------------------------- gate (+ x->fp16) ----------------------------------
__global__ void k_gate(const float* __restrict__ x, const float* __restrict__ gw) {
    int warp = threadIdx.x >> 5, lane = threadIdx.x & 31;
    int t = blockIdx.x * 8 + warp;
    float acc[En];
#pragma unroll
    for (int e = 0; e < En; ++e) acc[e] = 0.f;
    const float4* xr = reinterpret_cast<const float4*>(x + (size_t)t * Hn);
    uint2* xo = reinterpret_cast<uint2*>(c_x + (size_t)t * Hn);
#pragma unroll 4
    for (int it = 0; it < Hn / 128; ++it) {
        float4 xv = xr[lane + 32 * it];
        uint2 ov;
        ov.x = h2u(xv.x, xv.y);
        ov.y = h2u(xv.z, xv.w);
        xo[lane + 32 * it] = ov;
#pragma unroll
        for (int e = 0; e < En; ++e) {
            float4 wv = reinterpret_cast<const float4*>(gw + (size_t)e * Hn)[lane + 32 * it];
            acc[e] += xv.x * wv.x + xv.y * wv.y + xv.z * wv.z + xv.w * wv.w;
        }
    }
#pragma unroll
    for (int e = 0; e < En; ++e)
#pragma unroll
        for (int o = 16; o; o >>= 1) acc[e] += __shfl_xor_sync(0xffffffffu, acc[e], o);
    if (lane == 0) {
        int i0 = 0; float l0 = acc[0];
#pragma unroll
        for (int e = 1; e < En; ++e) if (acc[e] > l0) { l0 = acc[e]; i0 = e; }
        int i1 = -1; float l1 = -1e30f;
#pragma unroll
        for (int e = 0; e < En; ++e) if (e != i0 && acc[e] > l1) { l1 = acc[e]; i1 = e; }
        float e1 = expf(l1 - l0);
        float w0 = 1.f / (1.f + e1);
        float w1 = e1 / (1.f + e1);
        g_topk_i[2 * t]     = i0; g_topk_w[2 * t]     = w0;
        g_topk_i[2 * t + 1] = i1; g_topk_w[2 * t + 1] = w1;
    }
}

// ------------------------- fused routing (single CTA) ------------------------
__global__ void k_route() {
    __shared__ int cnt[En], off[En], cur[En];
    int tid = threadIdx.x;
    if (tid < En) cnt[tid] = 0;
    __syncthreads();
    for (int i = tid; i < Rn; i += 256) atomicAdd(&cnt[g_topk_i[i]], 1);
    __syncthreads();
    if (tid == 0) {
        int s = 0;
        for (int e = 0; e < En; ++e) { off[e] = s; s += cnt[e]; }
    }
    __syncthreads();
    if (tid < En) { g_cnt[tid] = cnt[tid]; g_off[tid] = off[tid]; cur[tid] = 0; }
    __syncthreads();
    for (int i = tid; i < Rn; i += 256) {
        int e = g_topk_i[i];
        int pos = off[e] + atomicAdd(&cur[e], 1);
        g_tok[pos] = i >> 1;
        g_w[pos]   = g_topk_w[i];
        g_slot[i]  = pos;
    }
}

// ------------------------- fp16 mma GEMM, f32-B on-the-fly -------------------
// A: fp16 via cp.async 4-stage (R8-proven). B: f32 LDG -> cvt -> STS,
// register double-buffered (load s+1 before mma(s)).
// VAR 0: gather(c_x) @ (wg|wu interleaved)[e] -> swiglu(+w) -> c_hr
// VAR 1: c_hr @ wd[e] -> g_yr
// VAR 2: c_x  @ (sg|su interleaved) -> swiglu -> c_hs
// VAR 3: c_hs @ sd (+routed combine) -> out
constexpr int ST  = 4;
constexpr int ABY = 128 * 64;
constexpr int BBY = 32 * 256;
constexpr int STG = ABY + BBY;
constexpr int DSM = ST * STG;    // 64KB

template <int VAR>
__global__ __launch_bounds__(256, 2)
void gemm_f16(const __half* __restrict__ Ag, const float* __restrict__ Bg,
              const float* __restrict__ Bu, float* __restrict__ Cg,
              __half* __restrict__ Ch) {
    constexpr int  KD   = (VAR == 1) ? 1024 : 2048;
    constexpr int  LDA  = (VAR == 1) ? 1024 : 2048;
    constexpr int  LDBF = (VAR == 0) ? 1024 : 2048;   // f32 source row stride
    constexpr int  LDO  = (VAR == 0) ? 1024 : 2048;
    constexpr bool GROUP  = (VAR < 2);
    constexpr bool GATHER = (VAR == 0);
    constexpr bool COMB   = (VAR == 3);
    constexpr bool SWI    = (VAR == 0 || VAR == 2);
    constexpr bool INTER  = SWI;                      // (g,u) interleave on the fly
    constexpr int  NIT  = KD / 32;

    const int tn = blockIdx.x, tm = blockIdx.y, e = blockIdx.z;
    int mcount = Tn, mbase = 0;
    if (GROUP) {
        mcount = g_cnt[e];
        if (tm * 128 >= mcount) return;
        mbase = g_off[e];
    }
    const float* Bpg = Bg;
    const float* Bpu = Bu;
    if (VAR == 0) { Bpg += (size_t)e * Hn * In; Bpu += (size_t)e * Hn * In; }
    if (VAR == 1) { Bpg += (size_t)e * In * Hn; }
    const int ncol0 = tn * 128;

    extern __shared__ char smraw[];
    const uint32_t smb = smem_u32(smraw);
    const int tid = threadIdx.x;

    // ---- A source (cp.async, unchanged from R8) ----
    int lr = tm * 128 + (tid >> 1);
    if (GROUP && lr >= mcount) lr = mcount - 1;
    const __half* arow;
    if (GATHER) arow = Ag + (size_t)g_tok[mbase + lr] * LDA;
    else        arow = Ag + (size_t)(mbase + lr) * LDA;
    arow += (tid & 1) * 16;
    const int arow_s = tid >> 1;
    const int ac0 = (tid & 1) * 2;
    uint32_t dsta0 = arow_s * 64 + (((ac0)     ^ ((arow_s >> 1) & 3)) << 4);
    uint32_t dsta1 = arow_s * 64 + (((ac0 + 1) ^ ((arow_s >> 1) & 3)) << 4);

    // ---- B source (f32 direct) ----
    const int bk = tid >> 3;              // k-row 0..31
    const int bc0 = (tid & 7) * 2;        // f16 chunk index (0..15, step 2)
    const float* bsg;
    const float* bsu = nullptr;
    if (INTER) {
        // interleaved cols [ncol0 + bc0*8, +16) = wg/wu cols [tn*64 + bc0*4, +8)
        bsg = Bpg + (size_t)bk * LDBF + tn * 64 + bc0 * 4;
        bsu = Bpu + (size_t)bk * LDBF + tn * 64 + bc0 * 4;
    } else {
        bsg = Bpg + (size_t)bk * LDBF + ncol0 + bc0 * 8;
    }
    const size_t bstep = (size_t)32 * LDBF;
    uint32_t dstb0 = ABY + bk * 256 + (((bc0)     ^ (bk & 7)) << 4);
    uint32_t dstb1 = ABY + bk * 256 + (((bc0 + 1) ^ (bk & 7)) << 4);

    uint32_t breg[8];
    auto ldg_b = [&](int sl) {
        if (INTER) {
            float4 ga = *reinterpret_cast<const float4*>(bsg + sl * bstep);
            float4 gb = *reinterpret_cast<const float4*>(bsg + sl * bstep + 4);
            float4 ua = *reinterpret_cast<const float4*>(bsu + sl * bstep);
            float4 ub = *reinterpret_cast<const float4*>(bsu + sl * bstep + 4);
            breg[0] = h2u(ga.x, ua.x); breg[1] = h2u(ga.y, ua.y);
            breg[2] = h2u(ga.z, ua.z); breg[3] = h2u(ga.w, ua.w);
            breg[4] = h2u(gb.x, ub.x); breg[5] = h2u(gb.y, ub.y);
            breg[6] = h2u(gb.z, ub.z); breg[7] = h2u(gb.w, ub.w);
        } else {
            float4 v0 = *reinterpret_cast<const float4*>(bsg + sl * bstep);
            float4 v1 = *reinterpret_cast<const float4*>(bsg + sl * bstep + 4);
            float4 v2 = *reinterpret_cast<const float4*>(bsg + sl * bstep + 8);
            float4 v3 = *reinterpret_cast<const float4*>(bsg + sl * bstep + 12);
            breg[0] = h2u(v0.x, v0.y); breg[1] = h2u(v0.z, v0.w);
            breg[2] = h2u(v1.x, v1.y); breg[3] = h2u(v1.z, v1.w);
            breg[4] = h2u(v2.x, v2.y); breg[5] = h2u(v2.z, v2.w);
            breg[6] = h2u(v3.x, v3.y); breg[7] = h2u(v3.z, v3.w);
        }
    };
    auto sts_b = [&](int sl) {
        uint32_t sb = smb + (sl % ST) * STG;
        uint4 a, b;
        a.x = breg[0]; a.y = breg[1]; a.z = breg[2]; a.w = breg[3];
        b.x = breg[4]; b.y = breg[5]; b.z = breg[6]; b.w = breg[7];
        *reinterpret_cast<uint4*>(smraw + (sb - smb) + dstb0) = a;
        *reinterpret_cast<uint4*>(smraw + (sb - smb) + dstb1) = b;
    };
    auto load_stage_a = [&](int sl) {
        uint32_t sb = smb + (sl % ST) * STG;
        const __half* as = arow + sl * 32;
        cpa16(sb + dsta0, as);
        cpa16(sb + dsta1, as + 8);
    };

#pragma unroll
    for (int s = 0; s < ST - 1; ++s) {
        if (s < NIT) load_stage_a(s);
        asm volatile("cp.async.commit_group;" ::: "memory");
    }
    ldg_b(0);

    float acc[4][4][4];
#pragma unroll
    for (int i = 0; i < 4; ++i)
#pragma unroll
        for (int j = 0; j < 4; ++j)
#pragma unroll
            for (int k = 0; k < 4; ++k) acc[i][j][k] = 0.f;

    const int w = tid >> 5, l = tid & 31;
    const int wm = (w >> 2) * 64, wn = (w & 3) * 32;
    const int l15 = l & 15, l16 = l >> 4;

    for (int s = 0; s < NIT; ++s) {
        sts_b(s);                                 // B(s) regs -> smem
        {
            int sl = s + ST - 1;
            if (sl < NIT) load_stage_a(sl);
            asm volatile("cp.async.commit_group;" ::: "memory");
        }
        if (s + 1 < NIT) ldg_b(s + 1);            // prefetch B(s+1), hidden by mma
        asm volatile("cp.async.wait_group 2;" ::: "memory");
        __syncthreads();

        uint32_t ab = smb + (s % ST) * STG, bb = ab + ABY;
#pragma unroll
        for (int ks = 0; ks < 2; ++ks) {
            uint32_t af[4][4], bf[2][4];
#pragma unroll
            for (int mi = 0; mi < 4; ++mi) {
                int m = wm + mi * 16 + l15;
                int c = ks * 2 + l16;
                ldsm4(af[mi], ab + m * 64 + ((c ^ ((m >> 1) & 3)) << 4));
            }
#pragma unroll
            for (int nj = 0; nj < 2; ++nj) {
                int k = ks * 16 + l15;
                int cn = (wn + nj * 16 + l16 * 8) >> 3;
                ldsm4t(bf[nj], bb + k * 256 + ((cn ^ (k & 7)) << 4));
            }
#pragma unroll
            for (int mi = 0; mi < 4; ++mi)
#pragma unroll
                for (int ni = 0; ni < 4; ++ni)
                    mma16(acc[mi][ni], af[mi], &bf[ni >> 1][(ni & 1) * 2]);
        }
        __syncthreads();   // protect buf (s%ST) B region before next STS cycle
    }

    const int qp = l >> 2, qr = l & 3;

    if (SWI) {
        // ---- swiglu epilogue: (g,u) adjacent cols; fp16 staged in smem ----
        __syncthreads();
        __half* sm = reinterpret_cast<__half*>(smraw);   // [128][72]
#pragma unroll
        for (int mi = 0; mi < 4; ++mi) {
#pragma unroll
            for (int h = 0; h < 2; ++h) {
                int row = wm + mi * 16 + qp + h * 8;
                float wgt = 1.f;
                if (GROUP) {
                    int cr = tm * 128 + row;
                    if (cr >= mcount) cr = mcount - 1;
                    wgt = g_w[mbase + cr];
                }
#pragma unroll
                for (int ni = 0; ni < 4; ++ni) {
                    int pi = (wn >> 1) + ni * 4 + qr;
                    float gv = acc[mi][ni][h * 2 + 0];
                    float uv = acc[mi][ni][h * 2 + 1];
                    float o = wgt * (gv / (1.f + expf(-gv))) * uv;
                    sm[row * 72 + pi] = __float2half_rn(o);
                }
            }
        }
        __syncthreads();
        int row = tid >> 1;
        int lrow = tm * 128 + row;
        if (!GROUP || lrow < mcount) {
            size_t rowi = (size_t)(mbase + lrow);
            const uint4* src = reinterpret_cast<const uint4*>(sm + row * 72 + (tid & 1) * 32);
            uint4* dst = reinterpret_cast<uint4*>(Ch + rowi * LDO + tn * 64 + (tid & 1) * 32);
#pragma unroll
            for (int q = 0; q < 4; ++q) dst[q] = src[q];
        }
        return;
    }

    // ---- f32 epilogue (VAR 1 and 3) ----
#pragma unroll
    for (int mi = 0; mi < 4; ++mi) {
#pragma unroll
        for (int h = 0; h < 2; ++h) {
            int lrow = tm * 128 + wm + mi * 16 + qp + h * 8;
            if (GROUP && lrow >= mcount) continue;
            size_t rowi = (size_t)(mbase + lrow);
#pragma unroll
            for (int ni = 0; ni < 4; ++ni) {
                int nc = ncol0 + wn + ni * 8 + 2 * qr;
                float2 v;
                v.x = acc[mi][ni][h * 2 + 0];
                v.y = acc[mi][ni][h * 2 + 1];
                if (COMB) {
                    int t = (int)rowi;
                    int s0 = g_slot[2 * t], s1 = g_slot[2 * t + 1];
                    float2 y0 = *reinterpret_cast<const float2*>(&g_yr[(size_t)s0 * Hn + nc]);
                    float2 y1 = *reinterpret_cast<const float2*>(&g_yr[(size_t)s1 * Hn + nc]);
                    v.x += y0.x + y1.x;
                    v.y += y0.y + y1.y;
                }
                *reinterpret_cast<float2*>(&Cg[rowi * 2048 + nc]) = v;
            }
        }
    }
}

// ------------------------- launch -------------------------------------------
extern "C" void kernel_launch(void* const* d_in, const int* in_sizes, int n_in,
                              void* d_out, int out_size) {
    (void)in_sizes; (void)n_in; (void)out_size;
    const float* x  = (const float*)d_in[0];
    const float* gw = (const float*)d_in[1];
    const float* wg = (const float*)d_in[2];
    const float* wu = (const float*)d_in[3];
    const float* wd = (const float*)d_in[4];
    const float* sg = (const float*)d_in[5];
    const float* su = (const float*)d_in[6];
    const float* sd = (const float*)d_in[7];
    float* out = (float*)d_out;

    cudaFuncSetAttribute(gemm_f16<0>, cudaFuncAttributeMaxDynamicSharedMemorySize, DSM);
    cudaFuncSetAttribute(gemm_f16<1>, cudaFuncAttributeMaxDynamicSharedMemorySize, DSM);
    cudaFuncSetAttribute(gemm_f16<2>, cudaFuncAttributeMaxDynamicSharedMemorySize, DSM);
    cudaFuncSetAttribute(gemm_f16<3>, cudaFuncAttributeMaxDynamicSharedMemorySize, DSM);

    __half *p_cx, *p_chr, *p_chs;
    float *p_gyr;
    cudaGetSymbolAddress((void**)&p_cx,  c_x);
    cudaGetSymbolAddress((void**)&p_chr, c_hr);
    cudaGetSymbolAddress((void**)&p_chs, c_hs);
    cudaGetSymbolAddress((void**)&p_gyr, g_yr);

    k_gate<<<Tn / 8, 256>>>(x, gw);                                                   // 1
    k_route<<<1, 256>>>();                                                            // 2
    gemm_f16<0><<<dim3(16, 32, 8), 256, DSM>>>(p_cx, wg, wu, nullptr, p_chr);         // 3 routed up+swiglu
    gemm_f16<1><<<dim3(16, 32, 8), 256, DSM>>>(p_chr, wd, nullptr, p_gyr, nullptr);   // 4 (profiled) routed down
    gemm_f16<2><<<dim3(32, 16, 1), 256, DSM>>>(p_cx, sg, su, nullptr, p_chs);         // 5 shared up+swiglu
    gemm_f16<3><<<dim3(16, 16, 1), 256, DSM>>>(p_chs, sd, nullptr, out, nullptr);     // 6 shared down+combine
}

// round 12
// speedup vs baseline: 1.3126x; 1.3126x over previous
#include <cuda_runtime.h>
#include <cuda_fp16.h>
#include <cstdint>
#include <math.h>

constexpr int Tn  = 2048;
constexpr int Hn  = 2048;
constexpr int In  = 1024;
constexpr int En  = 8;
constexpr int ISn = 2048;
constexpr int Rn  = 4096;

// ------------------------- scratch (device globals) -------------------------
__device__ __half c_yr [(size_t)Rn * Hn];         // routed down output (fp16)
__device__ __half c_x  [(size_t)Tn * Hn];
__device__ __half c_bu [(size_t)En * Hn * 2048];  // [e][h][(g,u) interleaved]
__device__ __half c_wd [(size_t)En * In * Hn];
__device__ __half c_bs [(size_t)Hn * 4096];       // [h][(g,u) interleaved]
__device__ __half c_sd [(size_t)ISn * Hn];
__device__ __half c_hr [(size_t)Rn * In];
__device__ __half c_hs [(size_t)Tn * ISn];
__device__ int   g_tok[Rn];
__device__ float g_w  [Rn];
__device__ int   g_slot[Rn];
__device__ int   g_topk_i[Rn];
__device__ float g_topk_w[Rn];
__device__ int   g_cnt[En], g_off[En];

// ------------------------- PTX helpers --------------------------------------
__device__ __forceinline__ uint32_t smem_u32(const void* p) {
    uint32_t a;
    asm("{ .reg .u64 t; cvta.to.shared.u64 t, %1; cvt.u32.u64 %0, t; }" : "=r"(a) : "l"(p));
    return a;
}
__device__ __forceinline__ void cpa16(uint32_t dst, const void* src) {
    asm volatile("cp.async.cg.shared.global [%0], [%1], 16;" :: "r"(dst), "l"(src));
}
__device__ __forceinline__ void ldsm4(uint32_t* d, uint32_t a) {
    asm volatile("ldmatrix.sync.aligned.m8n8.x4.shared.b16 {%0,%1,%2,%3},[%4];"
                 : "=r"(d[0]), "=r"(d[1]), "=r"(d[2]), "=r"(d[3]) : "r"(a));
}
__device__ __forceinline__ void ldsm4t(uint32_t* d, uint32_t a) {
    asm volatile("ldmatrix.sync.aligned.m8n8.x4.trans.shared.b16 {%0,%1,%2,%3},[%4];"
                 : "=r"(d[0]), "=r"(d[1]), "=r"(d[2]), "=r"(d[3]) : "r"(a));
}
__device__ __forceinline__ void mma16(float* c, const uint32_t* a, const uint32_t* b) {
    asm volatile(
        "mma.sync.aligned.m16n8k16.row.col.f32.f16.f16.f32 "
        "{%0,%1,%2,%3},{%4,%5,%6,%7},{%8,%9},{%0,%1,%2,%3};"
        : "+f"(c[0]), "+f"(c[1]), "+f"(c[2]), "+f"(c[3])
        : "r"(a[0]), "r"(a[1]), "r"(a[2]), "r"(a[3]), "r"(b[0]), "r"(b[1]));
}
__device__ __forceinline__ uint32_t h2u(float a, float b) {
    __half2 h = __floats2half2_rn(a, b);
    return *reinterpret_cast<uint32_t*>(&h);
}

// ------------------------- gate (+ x->fp16), 2 warps/token -------------------
__global__ void k_gate(const float* __restrict__ x, const float* __restrict__ gw) {
    __shared__ float red[4][2][En];
    int wid = threadIdx.x >> 5, lane = threadIdx.x & 31;
    int tp = wid >> 1, hf = wid & 1;           // token-in-block, half
    int t = blockIdx.x * 4 + tp;
    float acc[En];
#pragma unroll
    for (int e = 0; e < En; ++e) acc[e] = 0.f;
    const float4* xr = reinterpret_cast<const float4*>(x + (size_t)t * Hn);
    uint2* xo = reinterpret_cast<uint2*>(c_x + (size_t)t * Hn);
#pragma unroll
    for (int j = 0; j < 8; ++j) {
        int it = hf * 8 + j;
        float4 xv = xr[lane + 32 * it];
        uint2 ov;
        ov.x = h2u(xv.x, xv.y);
        ov.y = h2u(xv.z, xv.w);
        xo[lane + 32 * it] = ov;
#pragma unroll
        for (int e = 0; e < En; ++e) {
            float4 wv = reinterpret_cast<const float4*>(gw + (size_t)e * Hn)[lane + 32 * it];
            acc[e] += xv.x * wv.x + xv.y * wv.y + xv.z * wv.z + xv.w * wv.w;
        }
    }
#pragma unroll
    for (int e = 0; e < En; ++e)
#pragma unroll
        for (int o = 16; o; o >>= 1) acc[e] += __shfl_xor_sync(0xffffffffu, acc[e], o);
    if (lane == 0) {
#pragma unroll
        for (int e = 0; e < En; ++e) red[tp][hf][e] = acc[e];
    }
    __syncthreads();
    if (hf == 0 && lane == 0) {
        float sc[En];
#pragma unroll
        for (int e = 0; e < En; ++e) sc[e] = red[tp][0][e] + red[tp][1][e];
        int i0 = 0; float l0 = sc[0];
#pragma unroll
        for (int e = 1; e < En; ++e) if (sc[e] > l0) { l0 = sc[e]; i0 = e; }
        int i1 = -1; float l1 = -1e30f;
#pragma unroll
        for (int e = 0; e < En; ++e) if (e != i0 && sc[e] > l1) { l1 = sc[e]; i1 = e; }
        float e1 = expf(l1 - l0);
        float w0 = 1.f / (1.f + e1);
        float w1 = e1 / (1.f + e1);
        g_topk_i[2 * t]     = i0; g_topk_w[2 * t]     = w0;
        g_topk_i[2 * t + 1] = i1; g_topk_w[2 * t + 1] = w1;
    }
}

// ------------------------- fused routing (single CTA) ------------------------
__global__ void k_route() {
    __shared__ int cnt[En], off[En], cur[En];
    int tid = threadIdx.x;
    if (tid < En) cnt[tid] = 0;
    __syncthreads();
    for (int i = tid; i < Rn; i += 256) atomicAdd(&cnt[g_topk_i[i]], 1);
    __syncthreads();
    if (tid == 0) {
        int s = 0;
        for (int e = 0; e < En; ++e) { off[e] = s; s += cnt[e]; }
    }
    __syncthreads();
    if (tid < En) { g_cnt[tid] = cnt[tid]; g_off[tid] = off[tid]; cur[tid] = 0; }
    __syncthreads();
    for (int i = tid; i < Rn; i += 256) {
        int e = g_topk_i[i];
        int pos = off[e] + atomicAdd(&cur[e], 1);
        g_tok[pos] = i >> 1;
        g_w[pos]   = g_topk_w[i];
        g_slot[i]  = pos;
    }
}

// ------------------------- weight conversion ---------------------------------
__device__ __forceinline__ void cvt_pair_seg(const float* g, const float* u,
                                             __half* d, int rows, int inner,
                                             int gid, int gstride) {
    int i4 = inner / 4, tot = rows * i4;
    for (int q = gid; q < tot; q += gstride) {
        int r = q / i4, c = (q - r * i4) * 4;
        float4 gv = *reinterpret_cast<const float4*>(g + (size_t)r * inner + c);
        float4 uv = *reinterpret_cast<const float4*>(u + (size_t)r * inner + c);
        uint4 o;
        o.x = h2u(gv.x, uv.x);
        o.y = h2u(gv.y, uv.y);
        o.z = h2u(gv.z, uv.z);
        o.w = h2u(gv.w, uv.w);
        *reinterpret_cast<uint4*>(d + (size_t)r * 2 * inner + 2 * c) = o;
    }
}
__device__ __forceinline__ void cvt_seg(const float* s, __half* d, int n4,
                                        int gid, int gstride) {
    for (int i = gid; i < n4; i += gstride) {
        float4 v = reinterpret_cast<const float4*>(s)[i];
        uint2 o;
        o.x = h2u(v.x, v.y);
        o.y = h2u(v.z, v.w);
        reinterpret_cast<uint2*>(d)[i] = o;
    }
}
__global__ void k_cvt_bu(const float* __restrict__ wg, const float* __restrict__ wu) {
    int gid = blockIdx.x * 256 + threadIdx.x, gs = gridDim.x * 256;
    cvt_pair_seg(wg, wu, c_bu, En * Hn, In, gid, gs);
}
__global__ void k_cvt_rest(const float* __restrict__ wd, const float* __restrict__ sg,
                           const float* __restrict__ su, const float* __restrict__ sd) {
    int gid = blockIdx.x * 256 + threadIdx.x, gs = gridDim.x * 256;
    cvt_seg(wd, c_wd, En * In * Hn / 4, gid, gs);
    cvt_pair_seg(sg, su, c_bs, Hn, ISn, gid, gs);
    cvt_seg(sd, c_sd, ISn * Hn / 4, gid, gs);
}

// ------------------------- fp16 mma GEMM (R8-proven): 128x128x32, warp 64x32 -
constexpr int ST  = 4;
constexpr int ABY = 128 * 64;
constexpr int BBY = 32 * 256;
constexpr int STG = ABY + BBY;
constexpr int DSM = ST * STG;    // 64KB

template <int VAR>
__global__ __launch_bounds__(256, 2)
void gemm_f16(const __half* __restrict__ Ag, const __half* __restrict__ Bg,
              float* __restrict__ Cg, __half* __restrict__ Ch) {
    constexpr int  KD   = (VAR == 1) ? 1024 : 2048;
    constexpr int  LDA  = (VAR == 1) ? 1024 : 2048;
    constexpr int  LDB  = (VAR == 2) ? 4096 : 2048;
    constexpr int  LDO  = (VAR == 0) ? 1024 : 2048;
    constexpr bool GROUP  = (VAR < 2);
    constexpr bool GATHER = (VAR == 0);
    constexpr bool COMB   = (VAR == 3);
    constexpr bool SWI    = (VAR == 0 || VAR == 2);
    constexpr int  NIT  = KD / 32;

    const int tn = blockIdx.x, tm = blockIdx.y, e = blockIdx.z;
    int mcount = Tn, mbase = 0;
    if (GROUP) {
        mcount = g_cnt[e];
        if (tm * 128 >= mcount) return;
        mbase = g_off[e];
    }
    const __half* Bp = Bg;
    if (VAR == 0) Bp += (size_t)e * Hn * 2048;
    if (VAR == 1) Bp += (size_t)e * In * 2048;
    const int ncol0 = tn * 128;

    extern __shared__ char smraw[];
    const uint32_t smb = smem_u32(smraw);
    const int tid = threadIdx.x;

    // ---- A source ----
    int lr = tm * 128 + (tid >> 1);
    if (GROUP && lr >= mcount) lr = mcount - 1;
    const __half* arow;
    if (GATHER) arow = Ag + (size_t)g_tok[mbase + lr] * LDA;
    else        arow = Ag + (size_t)(mbase + lr) * LDA;
    arow += (tid & 1) * 16;
    const int arow_s = tid >> 1;
    const int ac0 = (tid & 1) * 2;
    uint32_t dsta0 = arow_s * 64 + (((ac0)     ^ ((arow_s >> 1) & 3)) << 4);
    uint32_t dsta1 = arow_s * 64 + (((ac0 + 1) ^ ((arow_s >> 1) & 3)) << 4);

    // ---- B source ----
    const int bk = tid >> 3;
    const int bc0 = (tid & 7) * 2;
    const __half* bsrc = Bp + (size_t)bk * LDB + ncol0 + bc0 * 8;
    uint32_t dstb0 = ABY + bk * 256 + (((bc0)     ^ (bk & 7)) << 4);
    uint32_t dstb1 = ABY + bk * 256 + (((bc0 + 1) ^ (bk & 7)) << 4);

    auto load_stage = [&](int sl) {
        uint32_t sb = smb + (sl % ST) * STG;
        const __half* as = arow + sl * 32;
        cpa16(sb + dsta0, as);
        cpa16(sb + dsta1, as + 8);
        const __half* bs = bsrc + (size_t)sl * 32 * LDB;
        cpa16(sb + dstb0, bs);
        cpa16(sb + dstb1, bs + 8);
    };

#pragma unroll
    for (int s = 0; s < ST - 1; ++s) {
        if (s < NIT) load_stage(s);
        asm volatile("cp.async.commit_group;" ::: "memory");
    }

    float acc[4][4][4];
#pragma unroll
    for (int i = 0; i < 4; ++i)
#pragma unroll
        for (int j = 0; j < 4; ++j)
#pragma unroll
            for (int k = 0; k < 4; ++k) acc[i][j][k] = 0.f;

    const int w = tid >> 5, l = tid & 31;
    const int wm = (w >> 2) * 64, wn = (w & 3) * 32;
    const int l15 = l & 15, l16 = l >> 4;

    for (int s = 0; s < NIT; ++s) {
        asm volatile("cp.async.wait_group 2;" ::: "memory");
        __syncthreads();
        {
            int sl = s + ST - 1;
            if (sl < NIT) load_stage(sl);
            asm volatile("cp.async.commit_group;" ::: "memory");
        }
        uint32_t ab = smb + (s % ST) * STG, bb = ab + ABY;
#pragma unroll
        for (int ks = 0; ks < 2; ++ks) {
            uint32_t af[4][4], bf[2][4];
#pragma unroll
            for (int mi = 0; mi < 4; ++mi) {
                int m = wm + mi * 16 + l15;
                int c = ks * 2 + l16;
                ldsm4(af[mi], ab + m * 64 + ((c ^ ((m >> 1) & 3)) << 4));
            }
#pragma unroll
            for (int nj = 0; nj < 2; ++nj) {
                int k = ks * 16 + l15;
                int cn = (wn + nj * 16 + l16 * 8) >> 3;
                ldsm4t(bf[nj], bb + k * 256 + ((cn ^ (k & 7)) << 4));
            }
#pragma unroll
            for (int mi = 0; mi < 4; ++mi)
#pragma unroll
                for (int ni = 0; ni < 4; ++ni)
                    mma16(acc[mi][ni], af[mi], &bf[ni >> 1][(ni & 1) * 2]);
        }
    }

    const int qp = l >> 2, qr = l & 3;

    if (SWI) {
        // ---- swiglu epilogue: (g,u) adjacent cols; fp16 staged in smem ----
        __syncthreads();
        __half* sm = reinterpret_cast<__half*>(smraw);   // [128][72]
#pragma unroll
        for (int mi = 0; mi < 4; ++mi) {
#pragma unroll
            for (int h = 0; h < 2; ++h) {
                int row = wm + mi * 16 + qp + h * 8;
                float wgt = 1.f;
                if (GROUP) {
                    int cr = tm * 128 + row;
                    if (cr >= mcount) cr = mcount - 1;
                    wgt = g_w[mbase + cr];
                }
#pragma unroll
                for (int ni = 0; ni < 4; ++ni) {
                    int pi = (wn >> 1) + ni * 4 + qr;
                    float gv = acc[mi][ni][h * 2 + 0];
                    float uv = acc[mi][ni][h * 2 + 1];
                    float o = wgt * (gv / (1.f + expf(-gv))) * uv;
                    sm[row * 72 + pi] = __float2half_rn(o);
                }
            }
        }
        __syncthreads();
        int row = tid >> 1;
        int lrow = tm * 128 + row;
        if (!GROUP || lrow < mcount) {
            size_t rowi = (size_t)(mbase + lrow);
            const uint4* src = reinterpret_cast<const uint4*>(sm + row * 72 + (tid & 1) * 32);
            uint4* dst = reinterpret_cast<uint4*>(Ch + rowi * LDO + tn * 64 + (tid & 1) * 32);
#pragma unroll
            for (int q = 0; q < 4; ++q) dst[q] = src[q];
        }
        return;
    }

    // ---- epilogue (VAR 1: fp16 -> c_yr; VAR 3: f32 out + combine) ----
#pragma unroll
    for (int mi = 0; mi < 4; ++mi) {
#pragma unroll
        for (int h = 0; h < 2; ++h) {
            int lrow = tm * 128 + wm + mi * 16 + qp + h * 8;
            if (GROUP && lrow >= mcount) continue;
            size_t rowi = (size_t)(mbase + lrow);
#pragma unroll
            for (int ni = 0; ni < 4; ++ni) {
                int nc = ncol0 + wn + ni * 8 + 2 * qr;
                float2 v;
                v.x = acc[mi][ni][h * 2 + 0];
                v.y = acc[mi][ni][h * 2 + 1];
                if (VAR == 1) {
                    *reinterpret_cast<uint32_t*>(&c_yr[rowi * Hn + nc]) = h2u(v.x, v.y);
                } else {
                    if (COMB) {
                        int t = (int)rowi;
                        int s0 = g_slot[2 * t], s1 = g_slot[2 * t + 1];
                        uint32_t u0 = *reinterpret_cast<const uint32_t*>(&c_yr[(size_t)s0 * Hn + nc]);
                        uint32_t u1 = *reinterpret_cast<const uint32_t*>(&c_yr[(size_t)s1 * Hn + nc]);
                        __half2 y0 = *reinterpret_cast<__half2*>(&u0);
                        __half2 y1 = *reinterpret_cast<__half2*>(&u1);
                        v.x += __low2float(y0)  + __low2float(y1);
                        v.y += __high2float(y0) + __high2float(y1);
                    }
                    *reinterpret_cast<float2*>(&Cg[rowi * 2048 + nc]) = v;
                }
            }
        }
    }
}

// ------------------------- launch -------------------------------------------
extern "C" void kernel_launch(void* const* d_in, const int* in_sizes, int n_in,
                              void* d_out, int out_size) {
    (void)in_sizes; (void)n_in; (void)out_size;
    const float* x  = (const float*)d_in[0];
    const float* gw = (const float*)d_in[1];
    const float* wg = (const float*)d_in[2];
    const float* wu = (const float*)d_in[3];
    const float* wd = (const float*)d_in[4];
    const float* sg = (const float*)d_in[5];
    const float* su = (const float*)d_in[6];
    const float* sd = (const float*)d_in[7];
    float* out = (float*)d_out;

    cudaFuncSetAttribute(gemm_f16<0>, cudaFuncAttributeMaxDynamicSharedMemorySize, DSM);
    cudaFuncSetAttribute(gemm_f16<1>, cudaFuncAttributeMaxDynamicSharedMemorySize, DSM);
    cudaFuncSetAttribute(gemm_f16<2>, cudaFuncAttributeMaxDynamicSharedMemorySize, DSM);
    cudaFuncSetAttribute(gemm_f16<3>, cudaFuncAttributeMaxDynamicSharedMemorySize, DSM);

    __half *p_cx, *p_cbu, *p_cwd, *p_cbs, *p_csd, *p_chr, *p_chs;
    cudaGetSymbolAddress((void**)&p_cx,  c_x);
    cudaGetSymbolAddress((void**)&p_cbu, c_bu);
    cudaGetSymbolAddress((void**)&p_cwd, c_wd);
    cudaGetSymbolAddress((void**)&p_cbs, c_bs);
    cudaGetSymbolAddress((void**)&p_csd, c_sd);
    cudaGetSymbolAddress((void**)&p_chr, c_hr);
    cudaGetSymbolAddress((void**)&p_chs, c_hs);

    k_gate<<<Tn / 4, 256>>>(x, gw);                                            // 1
    k_route<<<1, 256>>>();                                                     // 2
    k_cvt_bu<<<2048, 256>>>(wg, wu);                                           // 3
    gemm_f16<0><<<dim3(16, 32, 8), 256, DSM>>>(p_cx, p_cbu, nullptr, p_chr);   // 4 (profiled)
    k_cvt_rest<<<2048, 256>>>(wd, sg, su, sd);                                 // 5
    gemm_f16<1><<<dim3(16, 32, 8), 256, DSM>>>(p_chr, p_cwd, nullptr, nullptr);// 6 routed down
    gemm_f16<2><<<dim3(32, 16, 1), 256, DSM>>>(p_cx, p_cbs, nullptr, p_chs);   // 7 shared up+swiglu
    gemm_f16<3><<<dim3(16, 16, 1), 256, DSM>>>(p_chs, p_csd, out, nullptr);    // 8 down+combine
}

// round 13
// speedup vs baseline: 1.4165x; 1.0791x over previous
#include <cuda_runtime.h>
#include <cuda_fp16.h>
#include <cstdint>
#include <math.h>

constexpr int Tn  = 2048;
constexpr int Hn  = 2048;
constexpr int In  = 1024;
constexpr int En  = 8;
constexpr int ISn = 2048;
constexpr int Rn  = 4096;

// ------------------------- scratch (device globals) -------------------------
__device__ __half c_yr [(size_t)Rn * Hn];         // routed down output (fp16)
__device__ __half c_x  [(size_t)Tn * Hn];
__device__ __half c_bu [(size_t)En * Hn * 2048];  // [e][h][(g,u) interleaved]
__device__ __half c_wd [(size_t)En * In * Hn];
__device__ __half c_bs [(size_t)Hn * 4096];       // [h][(g,u) interleaved]
__device__ __half c_sd [(size_t)ISn * Hn];
__device__ __half c_hr [(size_t)Rn * In];
__device__ __half c_hs [(size_t)Tn * ISn];
__device__ int   g_tok[Rn];
__device__ float g_w  [Rn];
__device__ int   g_slot[Rn];
__device__ int   g_topk_i[Rn];
__device__ float g_topk_w[Rn];
__device__ int   g_cnt[En], g_off[En];

// ------------------------- PTX helpers --------------------------------------
__device__ __forceinline__ uint32_t smem_u32(const void* p) {
    uint32_t a;
    asm("{ .reg .u64 t; cvta.to.shared.u64 t, %1; cvt.u32.u64 %0, t; }" : "=r"(a) : "l"(p));
    return a;
}
__device__ __forceinline__ void cpa16(uint32_t dst, const void* src) {
    asm volatile("cp.async.cg.shared.global [%0], [%1], 16;" :: "r"(dst), "l"(src));
}
__device__ __forceinline__ void ldsm4(uint32_t* d, uint32_t a) {
    asm volatile("ldmatrix.sync.aligned.m8n8.x4.shared.b16 {%0,%1,%2,%3},[%4];"
                 : "=r"(d[0]), "=r"(d[1]), "=r"(d[2]), "=r"(d[3]) : "r"(a));
}
__device__ __forceinline__ void ldsm4t(uint32_t* d, uint32_t a) {
    asm volatile("ldmatrix.sync.aligned.m8n8.x4.trans.shared.b16 {%0,%1,%2,%3},[%4];"
                 : "=r"(d[0]), "=r"(d[1]), "=r"(d[2]), "=r"(d[3]) : "r"(a));
}
__device__ __forceinline__ void mma16(float* c, const uint32_t* a, const uint32_t* b) {
    asm volatile(
        "mma.sync.aligned.m16n8k16.row.col.f32.f16.f16.f32 "
        "{%0,%1,%2,%3},{%4,%5,%6,%7},{%8,%9},{%0,%1,%2,%3};"
        : "+f"(c[0]), "+f"(c[1]), "+f"(c[2]), "+f"(c[3])
        : "r"(a[0]), "r"(a[1]), "r"(a[2]), "r"(a[3]), "r"(b[0]), "r"(b[1]));
}
__device__ __forceinline__ uint32_t h2u(float a, float b) {
    __half2 h = __floats2half2_rn(a, b);
    return *reinterpret_cast<uint32_t*>(&h);
}

// ------------------------- conversion helpers --------------------------------
__device__ __forceinline__ void cvt_pair_seg(const float* g, const float* u,
                                             __half* d, int rows, int inner,
                                             int gid, int gstride) {
    int i4 = inner / 4, tot = rows * i4;
    for (int q = gid; q < tot; q += gstride) {
        int r = q / i4, c = (q - r * i4) * 4;
        float4 gv = *reinterpret_cast<const float4*>(g + (size_t)r * inner + c);
        float4 uv = *reinterpret_cast<const float4*>(u + (size_t)r * inner + c);
        uint4 o;
        o.x = h2u(gv.x, uv.x);
        o.y = h2u(gv.y, uv.y);
        o.z = h2u(gv.z, uv.z);
        o.w = h2u(gv.w, uv.w);
        *reinterpret_cast<uint4*>(d + (size_t)r * 2 * inner + 2 * c) = o;
    }
}
__device__ __forceinline__ void cvt_seg(const float* s, __half* d, int n4,
                                        int gid, int gstride) {
    for (int i = gid; i < n4; i += gstride) {
        float4 v = reinterpret_cast<const float4*>(s)[i];
        uint2 o;
        o.x = h2u(v.x, v.y);
        o.y = h2u(v.z, v.w);
        reinterpret_cast<uint2*>(d)[i] = o;
    }
}

// ------------------------- gate (+x->fp16) fused with cvt_bu -----------------
__global__ void k_gate_cvt(const float* __restrict__ x, const float* __restrict__ gw,
                           const float* __restrict__ wg, const float* __restrict__ wu) {
    if (blockIdx.x >= 512) {
        // ---- cvt_bu co-tenant CTAs ----
        int gid = (blockIdx.x - 512) * 256 + threadIdx.x;
        cvt_pair_seg(wg, wu, c_bu, En * Hn, In, gid, 2048 * 256);
        return;
    }
    // ---- gate: 2 warps per token ----
    __shared__ float red[4][2][En];
    int wid = threadIdx.x >> 5, lane = threadIdx.x & 31;
    int tp = wid >> 1, hf = wid & 1;
    int t = blockIdx.x * 4 + tp;
    float acc[En];
#pragma unroll
    for (int e = 0; e < En; ++e) acc[e] = 0.f;
    const float4* xr = reinterpret_cast<const float4*>(x + (size_t)t * Hn);
    uint2* xo = reinterpret_cast<uint2*>(c_x + (size_t)t * Hn);
#pragma unroll
    for (int j = 0; j < 8; ++j) {
        int it = hf * 8 + j;
        float4 xv = xr[lane + 32 * it];
        uint2 ov;
        ov.x = h2u(xv.x, xv.y);
        ov.y = h2u(xv.z, xv.w);
        xo[lane + 32 * it] = ov;
#pragma unroll
        for (int e = 0; e < En; ++e) {
            float4 wv = reinterpret_cast<const float4*>(gw + (size_t)e * Hn)[lane + 32 * it];
            acc[e] += xv.x * wv.x + xv.y * wv.y + xv.z * wv.z + xv.w * wv.w;
        }
    }
#pragma unroll
    for (int e = 0; e < En; ++e)
#pragma unroll
        for (int o = 16; o; o >>= 1) acc[e] += __shfl_xor_sync(0xffffffffu, acc[e], o);
    if (lane == 0) {
#pragma unroll
        for (int e = 0; e < En; ++e) red[tp][hf][e] = acc[e];
    }
    __syncthreads();
    if (hf == 0 && lane == 0) {
        float sc[En];
#pragma unroll
        for (int e = 0; e < En; ++e) sc[e] = red[tp][0][e] + red[tp][1][e];
        int i0 = 0; float l0 = sc[0];
#pragma unroll
        for (int e = 1; e < En; ++e) if (sc[e] > l0) { l0 = sc[e]; i0 = e; }
        int i1 = -1; float l1 = -1e30f;
#pragma unroll
        for (int e = 0; e < En; ++e) if (e != i0 && sc[e] > l1) { l1 = sc[e]; i1 = e; }
        float e1 = expf(l1 - l0);
        float w0 = 1.f / (1.f + e1);
        float w1 = e1 / (1.f + e1);
        g_topk_i[2 * t]     = i0; g_topk_w[2 * t]     = w0;
        g_topk_i[2 * t + 1] = i1; g_topk_w[2 * t + 1] = w1;
    }
}

// ------------------------- fused routing (single CTA) ------------------------
__global__ void k_route() {
    __shared__ int cnt[En], off[En], cur[En];
    int tid = threadIdx.x;
    if (tid < En) cnt[tid] = 0;
    __syncthreads();
    for (int i = tid; i < Rn; i += 256) atomicAdd(&cnt[g_topk_i[i]], 1);
    __syncthreads();
    if (tid == 0) {
        int s = 0;
        for (int e = 0; e < En; ++e) { off[e] = s; s += cnt[e]; }
    }
    __syncthreads();
    if (tid < En) { g_cnt[tid] = cnt[tid]; g_off[tid] = off[tid]; cur[tid] = 0; }
    __syncthreads();
    for (int i = tid; i < Rn; i += 256) {
        int e = g_topk_i[i];
        int pos = off[e] + atomicAdd(&cur[e], 1);
        g_tok[pos] = i >> 1;
        g_w[pos]   = g_topk_w[i];
        g_slot[i]  = pos;
    }
}

// ------------------------- fp16 mma GEMM body (R8/R12-proven) ----------------
constexpr int ST  = 4;
constexpr int ABY = 128 * 64;
constexpr int BBY = 32 * 256;
constexpr int STG = ABY + BBY;
constexpr int DSM = ST * STG;    // 64KB

template <int VAR>
__device__ __forceinline__ void gemm_body(const __half* __restrict__ Ag,
                                          const __half* __restrict__ Bg,
                                          float* __restrict__ Cg,
                                          __half* __restrict__ Ch,
                                          int tn, int tm, int e) {
    constexpr int  KD   = (VAR == 1) ? 1024 : 2048;
    constexpr int  LDA  = (VAR == 1) ? 1024 : 2048;
    constexpr int  LDB  = (VAR == 2) ? 4096 : 2048;
    constexpr int  LDO  = (VAR == 0) ? 1024 : 2048;
    constexpr bool GROUP  = (VAR < 2);
    constexpr bool GATHER = (VAR == 0);
    constexpr bool COMB   = (VAR == 3);
    constexpr bool SWI    = (VAR == 0 || VAR == 2);
    constexpr int  NIT  = KD / 32;

    int mcount = Tn, mbase = 0;
    if (GROUP) {
        mcount = g_cnt[e];
        if (tm * 128 >= mcount) return;
        mbase = g_off[e];
    }
    const __half* Bp = Bg;
    if (VAR == 0) Bp += (size_t)e * Hn * 2048;
    if (VAR == 1) Bp += (size_t)e * In * 2048;
    const int ncol0 = tn * 128;

    extern __shared__ char smraw[];
    const uint32_t smb = smem_u32(smraw);
    const int tid = threadIdx.x;

    // ---- A source ----
    int lr = tm * 128 + (tid >> 1);
    if (GROUP && lr >= mcount) lr = mcount - 1;
    const __half* arow;
    if (GATHER) arow = Ag + (size_t)g_tok[mbase + lr] * LDA;
    else        arow = Ag + (size_t)(mbase + lr) * LDA;
    arow += (tid & 1) * 16;
    const int arow_s = tid >> 1;
    const int ac0 = (tid & 1) * 2;
    uint32_t dsta0 = arow_s * 64 + (((ac0)     ^ ((arow_s >> 1) & 3)) << 4);
    uint32_t dsta1 = arow_s * 64 + (((ac0 + 1) ^ ((arow_s >> 1) & 3)) << 4);

    // ---- B source ----
    const int bk = tid >> 3;
    const int bc0 = (tid & 7) * 2;
    const __half* bsrc = Bp + (size_t)bk * LDB + ncol0 + bc0 * 8;
    uint32_t dstb0 = ABY + bk * 256 + (((bc0)     ^ (bk & 7)) << 4);
    uint32_t dstb1 = ABY + bk * 256 + (((bc0 + 1) ^ (bk & 7)) << 4);

    auto load_stage = [&](int sl) {
        uint32_t sb = smb + (sl % ST) * STG;
        const __half* as = arow + sl * 32;
        cpa16(sb + dsta0, as);
        cpa16(sb + dsta1, as + 8);
        const __half* bs = bsrc + (size_t)sl * 32 * LDB;
        cpa16(sb + dstb0, bs);
        cpa16(sb + dstb1, bs + 8);
    };

#pragma unroll
    for (int s = 0; s < ST - 1; ++s) {
        if (s < NIT) load_stage(s);
        asm volatile("cp.async.commit_group;" ::: "memory");
    }

    float acc[4][4][4];
#pragma unroll
    for (int i = 0; i < 4; ++i)
#pragma unroll
        for (int j = 0; j < 4; ++j)
#pragma unroll
            for (int k = 0; k < 4; ++k) acc[i][j][k] = 0.f;

    const int w = tid >> 5, l = tid & 31;
    const int wm = (w >> 2) * 64, wn = (w & 3) * 32;
    const int l15 = l & 15, l16 = l >> 4;

    for (int s = 0; s < NIT; ++s) {
        asm volatile("cp.async.wait_group 2;" ::: "memory");
        __syncthreads();
        {
            int sl = s + ST - 1;
            if (sl < NIT) load_stage(sl);
            asm volatile("cp.async.commit_group;" ::: "memory");
        }
        uint32_t ab = smb + (s % ST) * STG, bb = ab + ABY;
#pragma unroll
        for (int ks = 0; ks < 2; ++ks) {
            uint32_t af[4][4], bf[2][4];
#pragma unroll
            for (int mi = 0; mi < 4; ++mi) {
                int m = wm + mi * 16 + l15;
                int c = ks * 2 + l16;
                ldsm4(af[mi], ab + m * 64 + ((c ^ ((m >> 1) & 3)) << 4));
            }
#pragma unroll
            for (int nj = 0; nj < 2; ++nj) {
                int k = ks * 16 + l15;
                int cn = (wn + nj * 16 + l16 * 8) >> 3;
                ldsm4t(bf[nj], bb + k * 256 + ((cn ^ (k & 7)) << 4));
            }
#pragma unroll
            for (int mi = 0; mi < 4; ++mi)
#pragma unroll
                for (int ni = 0; ni < 4; ++ni)
                    mma16(acc[mi][ni], af[mi], &bf[ni >> 1][(ni & 1) * 2]);
        }
    }

    const int qp = l >> 2, qr = l & 3;

    if (SWI) {
        // ---- swiglu epilogue: (g,u) adjacent cols; fp16 staged in smem ----
        __syncthreads();
        __half* sm = reinterpret_cast<__half*>(smraw);   // [128][72]
#pragma unroll
        for (int mi = 0; mi < 4; ++mi) {
#pragma unroll
            for (int h = 0; h < 2; ++h) {
                int row = wm + mi * 16 + qp + h * 8;
                float wgt = 1.f;
                if (GROUP) {
                    int cr = tm * 128 + row;
                    if (cr >= mcount) cr = mcount - 1;
                    wgt = g_w[mbase + cr];
                }
#pragma unroll
                for (int ni = 0; ni < 4; ++ni) {
                    int pi = (wn >> 1) + ni * 4 + qr;
                    float gv = acc[mi][ni][h * 2 + 0];
                    float uv = acc[mi][ni][h * 2 + 1];
                    float o = wgt * (gv / (1.f + expf(-gv))) * uv;
                    sm[row * 72 + pi] = __float2half_rn(o);
                }
            }
        }
        __syncthreads();
        int row = tid >> 1;
        int lrow = tm * 128 + row;
        if (!GROUP || lrow < mcount) {
            size_t rowi = (size_t)(mbase + lrow);
            const uint4* src = reinterpret_cast<const uint4*>(sm + row * 72 + (tid & 1) * 32);
            uint4* dst = reinterpret_cast<uint4*>(Ch + rowi * LDO + tn * 64 + (tid & 1) * 32);
#pragma unroll
            for (int q = 0; q < 4; ++q) dst[q] = src[q];
        }
        return;
    }

    // ---- epilogue (VAR 1: fp16 -> c_yr; VAR 3: f32 out + combine) ----
#pragma unroll
    for (int mi = 0; mi < 4; ++mi) {
#pragma unroll
        for (int h = 0; h < 2; ++h) {
            int lrow = tm * 128 + wm + mi * 16 + qp + h * 8;
            if (GROUP && lrow >= mcount) continue;
            size_t rowi = (size_t)(mbase + lrow);
#pragma unroll
            for (int ni = 0; ni < 4; ++ni) {
                int nc = ncol0 + wn + ni * 8 + 2 * qr;
                float2 v;
                v.x = acc[mi][ni][h * 2 + 0];
                v.y = acc[mi][ni][h * 2 + 1];
                if (VAR == 1) {
                    *reinterpret_cast<uint32_t*>(&c_yr[rowi * Hn + nc]) = h2u(v.x, v.y);
                } else {
                    if (COMB) {
                        int t = (int)rowi;
                        int s0 = g_slot[2 * t], s1 = g_slot[2 * t + 1];
                        uint32_t u0 = *reinterpret_cast<const uint32_t*>(&c_yr[(size_t)s0 * Hn + nc]);
                        uint32_t u1 = *reinterpret_cast<const uint32_t*>(&c_yr[(size_t)s1 * Hn + nc]);
                        __half2 y0 = *reinterpret_cast<__half2*>(&u0);
                        __half2 y1 = *reinterpret_cast<__half2*>(&u1);
                        v.x += __low2float(y0)  + __low2float(y1);
                        v.y += __high2float(y0) + __high2float(y1);
                    }
                    *reinterpret_cast<float2*>(&Cg[rowi * 2048 + nc]) = v;
                }
            }
        }
    }
}

// ------------------------- kernels -------------------------------------------
// Up-proj (routed, z<8) with cvt_rest co-tenant CTAs at z==8.
__global__ __launch_bounds__(256, 2)
void k_gemm0(const float* __restrict__ wd, const float* __restrict__ sg,
             const float* __restrict__ su, const float* __restrict__ sd) {
    if (blockIdx.z == 8) {
        int gid = (blockIdx.y * 16 + blockIdx.x) * 256 + threadIdx.x;
        const int gs = 512 * 256;
        cvt_seg(wd, c_wd, En * In * Hn / 4, gid, gs);
        cvt_pair_seg(sg, su, c_bs, Hn, ISn, gid, gs);
        cvt_seg(sd, c_sd, ISn * Hn / 4, gid, gs);
        return;
    }
    gemm_body<0>(c_x, c_bu, nullptr, c_hr, blockIdx.x, blockIdx.y, blockIdx.z);
}

// Merged: routed down (z<8) + shared up (z==8).
__global__ __launch_bounds__(256, 2)
void k_gemm_mid() {
    if (blockIdx.z < 8) {
        if (blockIdx.x >= 16) return;
        gemm_body<1>(c_hr, c_wd, nullptr, nullptr, blockIdx.x, blockIdx.y, blockIdx.z);
    } else {
        if (blockIdx.y >= 16) return;
        gemm_body<2>(c_x, c_bs, nullptr, c_hs, blockIdx.x, blockIdx.y, 0);
    }
}

// Shared down + routed combine.
__global__ __launch_bounds__(256, 2)
void k_gemm3(float* __restrict__ out) {
    gemm_body<3>(c_hs, c_sd, out, nullptr, blockIdx.x, blockIdx.y, 0);
}

// ------------------------- launch -------------------------------------------
extern "C" void kernel_launch(void* const* d_in, const int* in_sizes, int n_in,
                              void* d_out, int out_size) {
    (void)in_sizes; (void)n_in; (void)out_size;
    const float* x  = (const float*)d_in[0];
    const float* gw = (const float*)d_in[1];
    const float* wg = (const float*)d_in[2];
    const float* wu = (const float*)d_in[3];
    const float* wd = (const float*)d_in[4];
    const float* sg = (const float*)d_in[5];
    const float* su = (const float*)d_in[6];
    const float* sd = (const float*)d_in[7];
    float* out = (float*)d_out;

    cudaFuncSetAttribute(k_gemm0,    cudaFuncAttributeMaxDynamicSharedMemorySize, DSM);
    cudaFuncSetAttribute(k_gemm_mid, cudaFuncAttributeMaxDynamicSharedMemorySize, DSM);
    cudaFuncSetAttribute(k_gemm3,    cudaFuncAttributeMaxDynamicSharedMemorySize, DSM);

    k_gate_cvt<<<2560, 256>>>(x, gw, wg, wu);              // 1: gate + x->f16 + cvt_bu
    k_route<<<1, 256>>>();                                 // 2
    k_gemm0<<<dim3(16, 32, 9), 256, DSM>>>(wd, sg, su, sd);// 3: routed up+swiglu (+cvt_rest)
    k_gemm_mid<<<dim3(32, 32, 9), 256, DSM>>>();           // 4 (profiled): routed down + shared up
    k_gemm3<<<dim3(16, 16, 1), 256, DSM>>>(out);           // 5: shared down + combine
}

// round 14
// speedup vs baseline: 1.4517x; 1.0248x over previous
#include <cuda_runtime.h>
#include <cuda_fp16.h>
#include <cstdint>
#include <math.h>

constexpr int Tn  = 2048;
constexpr int Hn  = 2048;
constexpr int In  = 1024;
constexpr int En  = 8;
constexpr int ISn = 2048;
constexpr int Rn  = 4096;

// ------------------------- scratch (device globals) -------------------------
__device__ __half c_yr [(size_t)Rn * Hn];         // routed down output (fp16)
__device__ __half c_x  [(size_t)Tn * Hn];
__device__ __half c_bu [(size_t)En * Hn * 2048];  // [e][h][(g,u) interleaved]
__device__ __half c_wd [(size_t)En * In * Hn];
__device__ __half c_bs [(size_t)Hn * 4096];       // [h][(g,u) interleaved]
__device__ __half c_sd [(size_t)ISn * Hn];
__device__ __half c_hr [(size_t)Rn * In];
__device__ __half c_hs [(size_t)Tn * ISn];
__device__ int   g_tok[Rn];
__device__ float g_w  [Rn];
__device__ int   g_slot[Rn];
__device__ int   g_topk_i[Rn];
__device__ float g_topk_w[Rn];
__device__ int   g_cnt[En], g_off[En];

// ------------------------- PTX helpers --------------------------------------
__device__ __forceinline__ uint32_t smem_u32(const void* p) {
    uint32_t a;
    asm("{ .reg .u64 t; cvta.to.shared.u64 t, %1; cvt.u32.u64 %0, t; }" : "=r"(a) : "l"(p));
    return a;
}
__device__ __forceinline__ void cpa16(uint32_t dst, const void* src) {
    asm volatile("cp.async.cg.shared.global [%0], [%1], 16;" :: "r"(dst), "l"(src));
}
__device__ __forceinline__ void ldsm4(uint32_t* d, uint32_t a) {
    asm volatile("ldmatrix.sync.aligned.m8n8.x4.shared.b16 {%0,%1,%2,%3},[%4];"
                 : "=r"(d[0]), "=r"(d[1]), "=r"(d[2]), "=r"(d[3]) : "r"(a));
}
__device__ __forceinline__ void ldsm4t(uint32_t* d, uint32_t a) {
    asm volatile("ldmatrix.sync.aligned.m8n8.x4.trans.shared.b16 {%0,%1,%2,%3},[%4];"
                 : "=r"(d[0]), "=r"(d[1]), "=r"(d[2]), "=r"(d[3]) : "r"(a));
}
__device__ __forceinline__ void mma16(float* c, const uint32_t* a, const uint32_t* b) {
    asm volatile(
        "mma.sync.aligned.m16n8k16.row.col.f32.f16.f16.f32 "
        "{%0,%1,%2,%3},{%4,%5,%6,%7},{%8,%9},{%0,%1,%2,%3};"
        : "+f"(c[0]), "+f"(c[1]), "+f"(c[2]), "+f"(c[3])
        : "r"(a[0]), "r"(a[1]), "r"(a[2]), "r"(a[3]), "r"(b[0]), "r"(b[1]));
}
__device__ __forceinline__ uint32_t h2u(float a, float b) {
    __half2 h = __floats2half2_rn(a, b);
    return *reinterpret_cast<uint32_t*>(&h);
}

// ------------------------- conversion helpers --------------------------------
__device__ __forceinline__ void cvt_pair_seg(const float* g, const float* u,
                                             __half* d, int rows, int inner,
                                             int gid, int gstride) {
    int i4 = inner / 4, tot = rows * i4;
    for (int q = gid; q < tot; q += gstride) {
        int r = q / i4, c = (q - r * i4) * 4;
        float4 gv = *reinterpret_cast<const float4*>(g + (size_t)r * inner + c);
        float4 uv = *reinterpret_cast<const float4*>(u + (size_t)r * inner + c);
        uint4 o;
        o.x = h2u(gv.x, uv.x);
        o.y = h2u(gv.y, uv.y);
        o.z = h2u(gv.z, uv.z);
        o.w = h2u(gv.w, uv.w);
        *reinterpret_cast<uint4*>(d + (size_t)r * 2 * inner + 2 * c) = o;
    }
}
__device__ __forceinline__ void cvt_seg(const float* s, __half* d, int n4,
                                        int gid, int gstride) {
    for (int i = gid; i < n4; i += gstride) {
        float4 v = reinterpret_cast<const float4*>(s)[i];
        uint2 o;
        o.x = h2u(v.x, v.y);
        o.y = h2u(v.z, v.w);
        reinterpret_cast<uint2*>(d)[i] = o;
    }
}

// ------------------------- gate (+x->fp16) fused with cvt_bs -----------------
__global__ void k_gate_cvt(const float* __restrict__ x, const float* __restrict__ gw,
                           const float* __restrict__ sg, const float* __restrict__ su) {
    if (blockIdx.x >= 512) {
        // ---- cvt_bs co-tenant CTAs ----
        int gid = (blockIdx.x - 512) * 256 + threadIdx.x;
        cvt_pair_seg(sg, su, c_bs, Hn, ISn, gid, 512 * 256);
        return;
    }
    // ---- gate: 2 warps per token ----
    __shared__ float red[4][2][En];
    int wid = threadIdx.x >> 5, lane = threadIdx.x & 31;
    int tp = wid >> 1, hf = wid & 1;
    int t = blockIdx.x * 4 + tp;
    float acc[En];
#pragma unroll
    for (int e = 0; e < En; ++e) acc[e] = 0.f;
    const float4* xr = reinterpret_cast<const float4*>(x + (size_t)t * Hn);
    uint2* xo = reinterpret_cast<uint2*>(c_x + (size_t)t * Hn);
#pragma unroll
    for (int j = 0; j < 8; ++j) {
        int it = hf * 8 + j;
        float4 xv = xr[lane + 32 * it];
        uint2 ov;
        ov.x = h2u(xv.x, xv.y);
        ov.y = h2u(xv.z, xv.w);
        xo[lane + 32 * it] = ov;
#pragma unroll
        for (int e = 0; e < En; ++e) {
            float4 wv = reinterpret_cast<const float4*>(gw + (size_t)e * Hn)[lane + 32 * it];
            acc[e] += xv.x * wv.x + xv.y * wv.y + xv.z * wv.z + xv.w * wv.w;
        }
    }
#pragma unroll
    for (int e = 0; e < En; ++e)
#pragma unroll
        for (int o = 16; o; o >>= 1) acc[e] += __shfl_xor_sync(0xffffffffu, acc[e], o);
    if (lane == 0) {
#pragma unroll
        for (int e = 0; e < En; ++e) red[tp][hf][e] = acc[e];
    }
    __syncthreads();
    if (hf == 0 && lane == 0) {
        float sc[En];
#pragma unroll
        for (int e = 0; e < En; ++e) sc[e] = red[tp][0][e] + red[tp][1][e];
        int i0 = 0; float l0 = sc[0];
#pragma unroll
        for (int e = 1; e < En; ++e) if (sc[e] > l0) { l0 = sc[e]; i0 = e; }
        int i1 = -1; float l1 = -1e30f;
#pragma unroll
        for (int e = 0; e < En; ++e) if (e != i0 && sc[e] > l1) { l1 = sc[e]; i1 = e; }
        float e1 = expf(l1 - l0);
        float w0 = 1.f / (1.f + e1);
        float w1 = e1 / (1.f + e1);
        g_topk_i[2 * t]     = i0; g_topk_w[2 * t]     = w0;
        g_topk_i[2 * t + 1] = i1; g_topk_w[2 * t + 1] = w1;
    }
}

// ------------------------- fused routing (single CTA) ------------------------
__global__ void k_route() {
    __shared__ int cnt[En], off[En], cur[En];
    int tid = threadIdx.x;
    if (tid < En) cnt[tid] = 0;
    __syncthreads();
    for (int i = tid; i < Rn; i += 256) atomicAdd(&cnt[g_topk_i[i]], 1);
    __syncthreads();
    if (tid == 0) {
        int s = 0;
        for (int e = 0; e < En; ++e) { off[e] = s; s += cnt[e]; }
    }
    __syncthreads();
    if (tid < En) { g_cnt[tid] = cnt[tid]; g_off[tid] = off[tid]; cur[tid] = 0; }
    __syncthreads();
    for (int i = tid; i < Rn; i += 256) {
        int e = g_topk_i[i];
        int pos = off[e] + atomicAdd(&cur[e], 1);
        g_tok[pos] = i >> 1;
        g_w[pos]   = g_topk_w[i];
        g_slot[i]  = pos;
    }
}

// ------------------------- fp16 mma GEMM body (R8/R12-proven) ----------------
constexpr int ST  = 4;
constexpr int ABY = 128 * 64;
constexpr int BBY = 32 * 256;
constexpr int STG = ABY + BBY;
constexpr int DSM = ST * STG;    // 64KB

template <int VAR>
__device__ __forceinline__ void gemm_body(const __half* __restrict__ Ag,
                                          const __half* __restrict__ Bg,
                                          float* __restrict__ Cg,
                                          __half* __restrict__ Ch,
                                          int tn, int tm, int e) {
    constexpr int  KD   = (VAR == 1) ? 1024 : 2048;
    constexpr int  LDA  = (VAR == 1) ? 1024 : 2048;
    constexpr int  LDB  = (VAR == 2) ? 4096 : 2048;
    constexpr int  LDO  = (VAR == 0) ? 1024 : 2048;
    constexpr bool GROUP  = (VAR < 2);
    constexpr bool GATHER = (VAR == 0);
    constexpr bool COMB   = (VAR == 3);
    constexpr bool SWI    = (VAR == 0 || VAR == 2);
    constexpr int  NIT  = KD / 32;

    int mcount = Tn, mbase = 0;
    if (GROUP) {
        mcount = g_cnt[e];
        if (tm * 128 >= mcount) return;
        mbase = g_off[e];
    }
    const __half* Bp = Bg;
    if (VAR == 0) Bp += (size_t)e * Hn * 2048;
    if (VAR == 1) Bp += (size_t)e * In * 2048;
    const int ncol0 = tn * 128;

    extern __shared__ char smraw[];
    const uint32_t smb = smem_u32(smraw);
    const int tid = threadIdx.x;

    // ---- A source ----
    int lr = tm * 128 + (tid >> 1);
    if (GROUP && lr >= mcount) lr = mcount - 1;
    const __half* arow;
    if (GATHER) arow = Ag + (size_t)g_tok[mbase + lr] * LDA;
    else        arow = Ag + (size_t)(mbase + lr) * LDA;
    arow += (tid & 1) * 16;
    const int arow_s = tid >> 1;
    const int ac0 = (tid & 1) * 2;
    uint32_t dsta0 = arow_s * 64 + (((ac0)     ^ ((arow_s >> 1) & 3)) << 4);
    uint32_t dsta1 = arow_s * 64 + (((ac0 + 1) ^ ((arow_s >> 1) & 3)) << 4);

    // ---- B source ----
    const int bk = tid >> 3;
    const int bc0 = (tid & 7) * 2;
    const __half* bsrc = Bp + (size_t)bk * LDB + ncol0 + bc0 * 8;
    uint32_t dstb0 = ABY + bk * 256 + (((bc0)     ^ (bk & 7)) << 4);
    uint32_t dstb1 = ABY + bk * 256 + (((bc0 + 1) ^ (bk & 7)) << 4);

    auto load_stage = [&](int sl) {
        uint32_t sb = smb + (sl % ST) * STG;
        const __half* as = arow + sl * 32;
        cpa16(sb + dsta0, as);
        cpa16(sb + dsta1, as + 8);
        const __half* bs = bsrc + (size_t)sl * 32 * LDB;
        cpa16(sb + dstb0, bs);
        cpa16(sb + dstb1, bs + 8);
    };

#pragma unroll
    for (int s = 0; s < ST - 1; ++s) {
        if (s < NIT) load_stage(s);
        asm volatile("cp.async.commit_group;" ::: "memory");
    }

    float acc[4][4][4];
#pragma unroll
    for (int i = 0; i < 4; ++i)
#pragma unroll
        for (int j = 0; j < 4; ++j)
#pragma unroll
            for (int k = 0; k < 4; ++k) acc[i][j][k] = 0.f;

    const int w = tid >> 5, l = tid & 31;
    const int wm = (w >> 2) * 64, wn = (w & 3) * 32;
    const int l15 = l & 15, l16 = l >> 4;

    for (int s = 0; s < NIT; ++s) {
        asm volatile("cp.async.wait_group 2;" ::: "memory");
        __syncthreads();
        {
            int sl = s + ST - 1;
            if (sl < NIT) load_stage(sl);
            asm volatile("cp.async.commit_group;" ::: "memory");
        }
        uint32_t ab = smb + (s % ST) * STG, bb = ab + ABY;
#pragma unroll
        for (int ks = 0; ks < 2; ++ks) {
            uint32_t af[4][4], bf[2][4];
#pragma unroll
            for (int mi = 0; mi < 4; ++mi) {
                int m = wm + mi * 16 + l15;
                int c = ks * 2 + l16;
                ldsm4(af[mi], ab + m * 64 + ((c ^ ((m >> 1) & 3)) << 4));
            }
#pragma unroll
            for (int nj = 0; nj < 2; ++nj) {
                int k = ks * 16 + l15;
                int cn = (wn + nj * 16 + l16 * 8) >> 3;
                ldsm4t(bf[nj], bb + k * 256 + ((cn ^ (k & 7)) << 4));
            }
#pragma unroll
            for (int mi = 0; mi < 4; ++mi)
#pragma unroll
                for (int ni = 0; ni < 4; ++ni)
                    mma16(acc[mi][ni], af[mi], &bf[ni >> 1][(ni & 1) * 2]);
        }
    }

    const int qp = l >> 2, qr = l & 3;

    if (SWI) {
        // ---- swiglu epilogue: (g,u) adjacent cols; fp16 staged in smem ----
        __syncthreads();
        __half* sm = reinterpret_cast<__half*>(smraw);   // [128][72]
#pragma unroll
        for (int mi = 0; mi < 4; ++mi) {
#pragma unroll
            for (int h = 0; h < 2; ++h) {
                int row = wm + mi * 16 + qp + h * 8;
                float wgt = 1.f;
                if (GROUP) {
                    int cr = tm * 128 + row;
                    if (cr >= mcount) cr = mcount - 1;
                    wgt = g_w[mbase + cr];
                }
#pragma unroll
                for (int ni = 0; ni < 4; ++ni) {
                    int pi = (wn >> 1) + ni * 4 + qr;
                    float gv = acc[mi][ni][h * 2 + 0];
                    float uv = acc[mi][ni][h * 2 + 1];
                    float o = wgt * (gv / (1.f + expf(-gv))) * uv;
                    sm[row * 72 + pi] = __float2half_rn(o);
                }
            }
        }
        __syncthreads();
        int row = tid >> 1;
        int lrow = tm * 128 + row;
        if (!GROUP || lrow < mcount) {
            size_t rowi = (size_t)(mbase + lrow);
            const uint4* src = reinterpret_cast<const uint4*>(sm + row * 72 + (tid & 1) * 32);
            uint4* dst = reinterpret_cast<uint4*>(Ch + rowi * LDO + tn * 64 + (tid & 1) * 32);
#pragma unroll
            for (int q = 0; q < 4; ++q) dst[q] = src[q];
        }
        return;
    }

    // ---- epilogue (VAR 1: fp16 -> c_yr; VAR 3: f32 out + combine) ----
#pragma unroll
    for (int mi = 0; mi < 4; ++mi) {
#pragma unroll
        for (int h = 0; h < 2; ++h) {
            int lrow = tm * 128 + wm + mi * 16 + qp + h * 8;
            if (GROUP && lrow >= mcount) continue;
            size_t rowi = (size_t)(mbase + lrow);
#pragma unroll
            for (int ni = 0; ni < 4; ++ni) {
                int nc = ncol0 + wn + ni * 8 + 2 * qr;
                float2 v;
                v.x = acc[mi][ni][h * 2 + 0];
                v.y = acc[mi][ni][h * 2 + 1];
                if (VAR == 1) {
                    *reinterpret_cast<uint32_t*>(&c_yr[rowi * Hn + nc]) = h2u(v.x, v.y);
                } else {
                    if (COMB) {
                        int t = (int)rowi;
                        int s0 = g_slot[2 * t], s1 = g_slot[2 * t + 1];
                        uint32_t u0 = *reinterpret_cast<const uint32_t*>(&c_yr[(size_t)s0 * Hn + nc]);
                        uint32_t u1 = *reinterpret_cast<const uint32_t*>(&c_yr[(size_t)s1 * Hn + nc]);
                        __half2 y0 = *reinterpret_cast<__half2*>(&u0);
                        __half2 y1 = *reinterpret_cast<__half2*>(&u1);
                        v.x += __low2float(y0)  + __low2float(y1);
                        v.y += __high2float(y0) + __high2float(y1);
                    }
                    *reinterpret_cast<float2*>(&Cg[rowi * 2048 + nc]) = v;
                }
            }
        }
    }
}

// ------------------------- kernels -------------------------------------------
// Shared up-proj (z==0) with cvt_bu co-tenant CTAs at z==1.
__global__ __launch_bounds__(256, 2)
void k_gemm_su(const float* __restrict__ wg, const float* __restrict__ wu) {
    if (blockIdx.z == 1) {
        int gid = (blockIdx.y * 32 + blockIdx.x) * 256 + threadIdx.x;
        cvt_pair_seg(wg, wu, c_bu, En * Hn, In, gid, 512 * 256);
        return;
    }
    gemm_body<2>(c_x, c_bs, nullptr, c_hs, blockIdx.x, blockIdx.y, 0);
}

// Routed up-proj (z<8) with cvt wd/sd co-tenant CTAs at z==8.
__global__ __launch_bounds__(256, 2)
void k_gemm_ru(const float* __restrict__ wd, const float* __restrict__ sd) {
    if (blockIdx.z == 8) {
        int gid = (blockIdx.y * 16 + blockIdx.x) * 256 + threadIdx.x;
        const int gs = 512 * 256;
        cvt_seg(wd, c_wd, En * In * Hn / 4, gid, gs);
        cvt_seg(sd, c_sd, ISn * Hn / 4, gid, gs);
        return;
    }
    gemm_body<0>(c_x, c_bu, nullptr, c_hr, blockIdx.x, blockIdx.y, blockIdx.z);
}

// Routed down.
__global__ __launch_bounds__(256, 2)
void k_gemm_rd() {
    gemm_body<1>(c_hr, c_wd, nullptr, nullptr, blockIdx.x, blockIdx.y, blockIdx.z);
}

// Shared down + routed combine.
__global__ __launch_bounds__(256, 2)
void k_gemm_sd(float* __restrict__ out) {
    gemm_body<3>(c_hs, c_sd, out, nullptr, blockIdx.x, blockIdx.y, 0);
}

// ------------------------- launch -------------------------------------------
extern "C" void kernel_launch(void* const* d_in, const int* in_sizes, int n_in,
                              void* d_out, int out_size) {
    (void)in_sizes; (void)n_in; (void)out_size;
    const float* x  = (const float*)d_in[0];
    const float* gw = (const float*)d_in[1];
    const float* wg = (const float*)d_in[2];
    const float* wu = (const float*)d_in[3];
    const float* wd = (const float*)d_in[4];
    const float* sg = (const float*)d_in[5];
    const float* su = (const float*)d_in[6];
    const float* sd = (const float*)d_in[7];
    float* out = (float*)d_out;

    cudaFuncSetAttribute(k_gemm_su, cudaFuncAttributeMaxDynamicSharedMemorySize, DSM);
    cudaFuncSetAttribute(k_gemm_ru, cudaFuncAttributeMaxDynamicSharedMemorySize, DSM);
    cudaFuncSetAttribute(k_gemm_rd, cudaFuncAttributeMaxDynamicSharedMemorySize, DSM);
    cudaFuncSetAttribute(k_gemm_sd, cudaFuncAttributeMaxDynamicSharedMemorySize, DSM);

    k_gate_cvt<<<1024, 256>>>(x, gw, sg, su);              // 1: gate + x->f16 + cvt_bs
    k_route<<<1, 256>>>();                                 // 2
    k_gemm_su<<<dim3(32, 16, 2), 256, DSM>>>(wg, wu);      // 3: shared up+swiglu (+cvt_bu)
    k_gemm_ru<<<dim3(16, 32, 9), 256, DSM>>>(wd, sd);      // 4: routed up+swiglu (+cvt wd/sd)
    k_gemm_rd<<<dim3(16, 32, 8), 256, DSM>>>();            // 5: routed down -> c_yr
    k_gemm_sd<<<dim3(16, 16, 1), 256, DSM>>>(out);         // 6: shared down + combine
}